// round 1
// baseline (speedup 1.0000x reference)
#include <cuda_runtime.h>
#include <cuda_bf16.h>
#include <math.h>

// Shapes (from reference):
//   B=4, H=W=704, M=32, P=128, NN=129, R=1, GAIN=2.0
//   ref_boxes   : (B, M, 7)        float32
//   pred_class  : (B, 4, H, W)     float32
//   pred_regress: (B, 14, H, W)    float32
//   anchor      : (2, 7, H, W)     float32
//   pos_idx     : (B, P, 2)        int32
//   neg_idx     : (B, NN, 2)       int32
//   reg_idx     : (B, M, R, 2)     int32
// Output: scalar float = loss for batch b = B-1 only (reference returns losses[-1]).

#define HH 704
#define WW 704
#define HWSZ (HH * WW)
#define BM 32
#define PP 128
#define NNEG 129
#define RR 1
#define GAIN_F 2.0f

__device__ __forceinline__ float lse2(float a, float b) {
    float m = fmaxf(a, b);
    return m + logf(expf(a - m) + expf(b - m));
}

__device__ __forceinline__ float smooth_l1(float d) {
    float a = fabsf(d);
    return (a < 1.0f) ? 0.5f * d * d : a - 0.5f;
}

__global__ void loss_total_kernel(
    const float* __restrict__ ref_boxes,     // (B,M,7)
    const float* __restrict__ pred_class,    // (B,4,H,W)
    const float* __restrict__ pred_regress,  // (B,14,H,W)
    const float* __restrict__ anchor,        // (2,7,H,W)
    const int*   __restrict__ pos_idx,       // (B,P,2)
    const int*   __restrict__ neg_idx,       // (B,NN,2)
    const int*   __restrict__ reg_idx,       // (B,M,R,2)
    float* __restrict__ out)
{
    const int tid = threadIdx.x;
    const int nthr = blockDim.x;

    // batch b = 3 base offsets
    const float* pc = pred_class   + (size_t)3 * 4  * HWSZ;
    const float* pr = pred_regress + (size_t)3 * 14 * HWSZ;
    const float* rb = ref_boxes    + 3 * BM * 7;
    const int*   pi = pos_idx      + 3 * PP * 2;
    const int*   ni = neg_idx      + 3 * NNEG * 2;
    const int*   ri = reg_idx      + 3 * BM * RR * 2;

    float local = 0.0f;

    // ---- classification: positives (label 1) ----
    const float inv_P = 1.0f / (float)PP;
    for (int p = tid; p < PP; p += nthr) {
        int i0 = pi[2 * p + 0];
        int i1 = pi[2 * p + 1];
        int off = i0 * WW + i1;
        float l0 = pc[0 * HWSZ + off];
        float l1 = pc[1 * HWSZ + off];
        float l2 = pc[2 * HWSZ + off];
        float l3 = pc[3 * HWSZ + off];
        // -log_softmax([l0,l1])[1] = lse(l0,l1) - l1 ; same for (l2,l3)
        local += ((lse2(l0, l1) - l1) + (lse2(l2, l3) - l3)) * inv_P;
    }

    // ---- classification: negatives (label 0) ----
    const float inv_N = 1.0f / (float)NNEG;
    for (int n = tid; n < NNEG; n += nthr) {
        int i0 = ni[2 * n + 0];
        int i1 = ni[2 * n + 1];
        int off = i0 * WW + i1;
        float l0 = pc[0 * HWSZ + off];
        float l1 = pc[1 * HWSZ + off];
        float l2 = pc[2 * HWSZ + off];
        float l3 = pc[3 * HWSZ + off];
        local += ((lse2(l0, l1) - l0) + (lse2(l2, l3) - l2)) * inv_N;
    }

    // ---- regression (R=1): per m, mean over (R=1, a=2, c=7) = /14, summed over m ----
    const float inv_14 = 1.0f / 14.0f;
    for (int m = tid; m < BM; m += nthr) {
        int px = ri[2 * m + 0];   // R=1
        int py = ri[2 * m + 1];
        int off = px * WW + py;

        // ref box for this m
        float r0 = rb[m * 7 + 0], r1 = rb[m * 7 + 1], r2 = rb[m * 7 + 2];
        float r3 = rb[m * 7 + 3], r4 = rb[m * 7 + 4], r5 = rb[m * 7 + 5];
        float r6 = rb[m * 7 + 6];

        float reg_m = 0.0f;
        #pragma unroll
        for (int a = 0; a < 2; a++) {
            // anchor[a, c, px, py]
            float a0 = anchor[((size_t)a * 7 + 0) * HWSZ + off];
            float a1 = anchor[((size_t)a * 7 + 1) * HWSZ + off];
            float a2 = anchor[((size_t)a * 7 + 2) * HWSZ + off];
            float a3 = anchor[((size_t)a * 7 + 3) * HWSZ + off];
            float a4 = anchor[((size_t)a * 7 + 4) * HWSZ + off];
            float a5 = anchor[((size_t)a * 7 + 5) * HWSZ + off];
            float a6 = anchor[((size_t)a * 7 + 6) * HWSZ + off];

            float diag = sqrtf(a3 * a3 + a4 * a4);
            float o0 = (r0 - a0) / diag;
            float o1 = (r1 - a1) / diag;
            float o2 = (r2 - a2) / a5;
            float o3 = logf(r3 / a3);
            float o4 = logf(r4 / a4);
            float o5 = logf(r5 / a5);
            float dth = r6 - a6;
            float o6 = atan2f(sinf(dth), cosf(dth));

            // pbox[c] = pr[a*7+c, px, py]
            float p0 = pr[((size_t)(a * 7 + 0)) * HWSZ + off];
            float p1 = pr[((size_t)(a * 7 + 1)) * HWSZ + off];
            float p2 = pr[((size_t)(a * 7 + 2)) * HWSZ + off];
            float p3 = pr[((size_t)(a * 7 + 3)) * HWSZ + off];
            float p4 = pr[((size_t)(a * 7 + 4)) * HWSZ + off];
            float p5 = pr[((size_t)(a * 7 + 5)) * HWSZ + off];
            float p6 = pr[((size_t)(a * 7 + 6)) * HWSZ + off];

            reg_m += smooth_l1(p0 - o0) + smooth_l1(p1 - o1) + smooth_l1(p2 - o2)
                   + smooth_l1(p3 - o3) + smooth_l1(p4 - o4) + smooth_l1(p5 - o5)
                   + smooth_l1(p6 - o6);
        }
        local += GAIN_F * reg_m * inv_14;
    }

    // ---- block reduction ----
    __shared__ float sred[256];
    sred[tid] = local;
    __syncthreads();
    #pragma unroll
    for (int s = 128; s > 0; s >>= 1) {
        if (tid < s) sred[tid] += sred[tid + s];
        __syncthreads();
    }
    if (tid == 0) out[0] = sred[0];
}

extern "C" void kernel_launch(void* const* d_in, const int* in_sizes, int n_in,
                              void* d_out, int out_size) {
    const float* ref_boxes    = (const float*)d_in[0];
    const float* pred_class   = (const float*)d_in[1];
    const float* pred_regress = (const float*)d_in[2];
    const float* anchor       = (const float*)d_in[3];
    const int*   pos_idx      = (const int*)d_in[4];
    const int*   neg_idx      = (const int*)d_in[5];
    const int*   reg_idx      = (const int*)d_in[6];
    float* out = (float*)d_out;

    loss_total_kernel<<<1, 256>>>(ref_boxes, pred_class, pred_regress, anchor,
                                  pos_idx, neg_idx, reg_idx, out);
}

// round 3
// speedup vs baseline: 1.0036x; 1.0036x over previous
#include <cuda_runtime.h>
#include <cuda_bf16.h>
#include <math.h>

// B=4, H=W=704, M=32, P=128, NN=129, R=1, GAIN=2.0
// Only batch b=3 contributes (reference returns losses[-1]).
// One work-item per thread: tid 0..127 pos, 128..256 neg, 257..288 reg.

#define HH 704
#define WW 704
#define HWSZ (HH * WW)
#define BM 32
#define PP 128
#define NNEG 129
#define GAIN_F 2.0f
#define NTHR 320
#define NWARP (NTHR / 32)

__device__ __forceinline__ float lse2(float a, float b) {
    float m = fmaxf(a, b);
    return m + __logf(__expf(a - m) + __expf(b - m));
}

__device__ __forceinline__ float smooth_l1(float d) {
    float a = fabsf(d);
    return (a < 1.0f) ? 0.5f * d * d : a - 0.5f;
}

__global__ void __launch_bounds__(NTHR, 1) loss_total_kernel(
    const float* __restrict__ ref_boxes,     // (B,M,7)
    const float* __restrict__ pred_class,    // (B,4,H,W)
    const float* __restrict__ pred_regress,  // (B,14,H,W)
    const float* __restrict__ anchor,        // (2,7,H,W)
    const int*   __restrict__ pos_idx,       // (B,P,2)
    const int*   __restrict__ neg_idx,       // (B,NN,2)
    const int*   __restrict__ reg_idx,       // (B,M,1,2)
    float* __restrict__ out)
{
    const int tid = threadIdx.x;

    // batch b=3 base offsets
    const float* pc = pred_class   + (size_t)3 * 4  * HWSZ;
    const float* pr = pred_regress + (size_t)3 * 14 * HWSZ;
    const float* rb = ref_boxes    + 3 * BM * 7;
    const int2*  pi = (const int2*)(pos_idx + 3 * PP * 2);
    const int2*  ni = (const int2*)(neg_idx + 3 * NNEG * 2);
    const int2*  ri = (const int2*)(reg_idx + 3 * BM * 2);

    float local = 0.0f;

    if (tid < PP) {
        // ---- positive classification item (label 1) ----
        int2 idx = pi[tid];
        int off = idx.x * WW + idx.y;
        float l0 = pc[0 * HWSZ + off];
        float l1 = pc[1 * HWSZ + off];
        float l2 = pc[2 * HWSZ + off];
        float l3 = pc[3 * HWSZ + off];
        local = ((lse2(l0, l1) - l1) + (lse2(l2, l3) - l3)) * (1.0f / (float)PP);
    } else if (tid < PP + NNEG) {
        // ---- negative classification item (label 0) ----
        int2 idx = ni[tid - PP];
        int off = idx.x * WW + idx.y;
        float l0 = pc[0 * HWSZ + off];
        float l1 = pc[1 * HWSZ + off];
        float l2 = pc[2 * HWSZ + off];
        float l3 = pc[3 * HWSZ + off];
        local = ((lse2(l0, l1) - l0) + (lse2(l2, l3) - l2)) * (1.0f / (float)NNEG);
    } else if (tid < PP + NNEG + BM) {
        // ---- regression item (one m, R=1) ----
        int m = tid - (PP + NNEG);
        int2 idx = ri[m];
        int off = idx.x * WW + idx.y;

        float r0 = rb[m * 7 + 0], r1 = rb[m * 7 + 1], r2 = rb[m * 7 + 2];
        float r3 = rb[m * 7 + 3], r4 = rb[m * 7 + 4], r5 = rb[m * 7 + 5];
        float r6 = rb[m * 7 + 6];

        float reg_m = 0.0f;
        #pragma unroll
        for (int a = 0; a < 2; a++) {
            float a0 = anchor[((size_t)a * 7 + 0) * HWSZ + off];
            float a1 = anchor[((size_t)a * 7 + 1) * HWSZ + off];
            float a2 = anchor[((size_t)a * 7 + 2) * HWSZ + off];
            float a3 = anchor[((size_t)a * 7 + 3) * HWSZ + off];
            float a4 = anchor[((size_t)a * 7 + 4) * HWSZ + off];
            float a5 = anchor[((size_t)a * 7 + 5) * HWSZ + off];
            float a6 = anchor[((size_t)a * 7 + 6) * HWSZ + off];

            float p0 = pr[((size_t)(a * 7 + 0)) * HWSZ + off];
            float p1 = pr[((size_t)(a * 7 + 1)) * HWSZ + off];
            float p2 = pr[((size_t)(a * 7 + 2)) * HWSZ + off];
            float p3 = pr[((size_t)(a * 7 + 3)) * HWSZ + off];
            float p4 = pr[((size_t)(a * 7 + 4)) * HWSZ + off];
            float p5 = pr[((size_t)(a * 7 + 5)) * HWSZ + off];
            float p6 = pr[((size_t)(a * 7 + 6)) * HWSZ + off];

            float inv_diag = rsqrtf(a3 * a3 + a4 * a4);
            float o0 = (r0 - a0) * inv_diag;
            float o1 = (r1 - a1) * inv_diag;
            float o2 = (r2 - a2) / a5;
            float o3 = __logf(r3 / a3);
            float o4 = __logf(r4 / a4);
            float o5 = __logf(r5 / a5);
            // arctan2(sin(dth), cos(dth)) == wrap dth into (-pi, pi]
            float dth = r6 - a6;
            float o6 = dth - 6.28318530717958647692f *
                             rintf(dth * 0.15915494309189533577f);

            reg_m += smooth_l1(p0 - o0) + smooth_l1(p1 - o1) + smooth_l1(p2 - o2)
                   + smooth_l1(p3 - o3) + smooth_l1(p4 - o4) + smooth_l1(p5 - o5)
                   + smooth_l1(p6 - o6);
        }
        local = GAIN_F * reg_m * (1.0f / 14.0f);
    }

    // ---- reduction: warp shuffle, then one smem pass ----
    #pragma unroll
    for (int s = 16; s > 0; s >>= 1)
        local += __shfl_xor_sync(0xFFFFFFFFu, local, s);

    __shared__ float wsum[NWARP];
    const int wid = tid >> 5;
    const int lid = tid & 31;
    if (lid == 0) wsum[wid] = local;
    __syncthreads();

    if (wid == 0) {
        float v = (lid < NWARP) ? wsum[lid] : 0.0f;
        #pragma unroll
        for (int s = 8; s > 0; s >>= 1)
            v += __shfl_xor_sync(0xFFFFFFFFu, v, s);
        if (lid == 0) out[0] = v;
    }
}

extern "C" void kernel_launch(void* const* d_in, const int* in_sizes, int n_in,
                              void* d_out, int out_size) {
    const float* ref_boxes    = (const float*)d_in[0];
    const float* pred_class   = (const float*)d_in[1];
    const float* pred_regress = (const float*)d_in[2];
    const float* anchor       = (const float*)d_in[3];
    const int*   pos_idx      = (const int*)d_in[4];
    const int*   neg_idx      = (const int*)d_in[5];
    const int*   reg_idx      = (const int*)d_in[6];
    float* out = (float*)d_out;

    loss_total_kernel<<<1, NTHR>>>(ref_boxes, pred_class, pred_regress, anchor,
                                   pos_idx, neg_idx, reg_idx, out);
}

// round 4
// speedup vs baseline: 1.3023x; 1.2977x over previous
#include <cuda_runtime.h>
#include <cuda_bf16.h>
#include <math.h>

// B=4, H=W=704, M=32, P=128, NN=129, R=1, GAIN=2.0
// Only batch b=3 contributes (reference returns losses[-1]).
// 288 threads = 9 warps, one work-item per thread:
//   tid 0..127   -> pos item tid
//   tid 128..255 -> neg item tid-128   (tid 255 also does neg item 128)
//   tid 256..287 -> reg item tid-256

#define HH 704
#define WW 704
#define HWSZ (HH * WW)
#define BM 32
#define PP 128
#define NNEG 129
#define GAIN_F 2.0f
#define NTHR 288
#define NWARP (NTHR / 32)

__device__ __forceinline__ float lse2(float a, float b) {
    float m = fmaxf(a, b);
    return m + __logf(__expf(a - m) + __expf(b - m));
}

__device__ __forceinline__ float smooth_l1(float d) {
    float a = fabsf(d);
    return (a < 1.0f) ? 0.5f * d * d : a - 0.5f;
}

__device__ __forceinline__ float neg_item(const float* __restrict__ pc, int2 idx) {
    int off = idx.x * WW + idx.y;
    float l0 = pc[0 * HWSZ + off];
    float l1 = pc[1 * HWSZ + off];
    float l2 = pc[2 * HWSZ + off];
    float l3 = pc[3 * HWSZ + off];
    return ((lse2(l0, l1) - l0) + (lse2(l2, l3) - l2)) * (1.0f / (float)NNEG);
}

__global__ void __launch_bounds__(NTHR, 1) loss_total_kernel(
    const float* __restrict__ ref_boxes,     // (B,M,7)
    const float* __restrict__ pred_class,    // (B,4,H,W)
    const float* __restrict__ pred_regress,  // (B,14,H,W)
    const float* __restrict__ anchor,        // (2,7,H,W)
    const int*   __restrict__ pos_idx,       // (B,P,2)
    const int*   __restrict__ neg_idx,       // (B,NN,2)
    const int*   __restrict__ reg_idx,       // (B,M,1,2)
    float* __restrict__ out)
{
    const int tid = threadIdx.x;

    // batch b=3 base offsets
    const float* pc = pred_class   + (size_t)3 * 4  * HWSZ;
    const float* pr = pred_regress + (size_t)3 * 14 * HWSZ;
    const float* rb = ref_boxes    + 3 * BM * 7;
    const int2*  pi = (const int2*)(pos_idx + 3 * PP * 2);
    const int2*  ni = (const int2*)(neg_idx + 3 * NNEG * 2);
    const int2*  ri = (const int2*)(reg_idx + 3 * BM * 2);

    float local;

    if (tid < PP) {
        // ---- positive classification item (label 1) ----
        int2 idx = pi[tid];
        int off = idx.x * WW + idx.y;
        float l0 = pc[0 * HWSZ + off];
        float l1 = pc[1 * HWSZ + off];
        float l2 = pc[2 * HWSZ + off];
        float l3 = pc[3 * HWSZ + off];
        local = ((lse2(l0, l1) - l1) + (lse2(l2, l3) - l3)) * (1.0f / (float)PP);
    } else if (tid < 256) {
        // ---- negative classification item(s) (label 0) ----
        int2 idx = ni[tid - PP];
        local = neg_item(pc, idx);
        if (tid == 255) {
            // fold the 129th neg item into this thread (parallel to reg chains)
            local += neg_item(pc, ni[128]);
        }
    } else {
        // ---- regression item (one m, R=1) ----
        int m = tid - 256;
        int2 idx = ri[m];
        int off = idx.x * WW + idx.y;

        float r0 = rb[m * 7 + 0], r1 = rb[m * 7 + 1], r2 = rb[m * 7 + 2];
        float r3 = rb[m * 7 + 3], r4 = rb[m * 7 + 4], r5 = rb[m * 7 + 5];
        float r6 = rb[m * 7 + 6];

        float reg_m = 0.0f;
        #pragma unroll
        for (int a = 0; a < 2; a++) {
            float a0 = anchor[((size_t)a * 7 + 0) * HWSZ + off];
            float a1 = anchor[((size_t)a * 7 + 1) * HWSZ + off];
            float a2 = anchor[((size_t)a * 7 + 2) * HWSZ + off];
            float a3 = anchor[((size_t)a * 7 + 3) * HWSZ + off];
            float a4 = anchor[((size_t)a * 7 + 4) * HWSZ + off];
            float a5 = anchor[((size_t)a * 7 + 5) * HWSZ + off];
            float a6 = anchor[((size_t)a * 7 + 6) * HWSZ + off];

            float p0 = pr[((size_t)(a * 7 + 0)) * HWSZ + off];
            float p1 = pr[((size_t)(a * 7 + 1)) * HWSZ + off];
            float p2 = pr[((size_t)(a * 7 + 2)) * HWSZ + off];
            float p3 = pr[((size_t)(a * 7 + 3)) * HWSZ + off];
            float p4 = pr[((size_t)(a * 7 + 4)) * HWSZ + off];
            float p5 = pr[((size_t)(a * 7 + 5)) * HWSZ + off];
            float p6 = pr[((size_t)(a * 7 + 6)) * HWSZ + off];

            float inv_diag = rsqrtf(a3 * a3 + a4 * a4);
            float o0 = (r0 - a0) * inv_diag;
            float o1 = (r1 - a1) * inv_diag;
            float o2 = (r2 - a2) / a5;
            float o3 = __logf(r3 / a3);
            float o4 = __logf(r4 / a4);
            float o5 = __logf(r5 / a5);
            // arctan2(sin(dth), cos(dth)) == wrap dth into (-pi, pi]
            float dth = r6 - a6;
            float o6 = dth - 6.28318530717958647692f *
                             rintf(dth * 0.15915494309189533577f);

            reg_m += smooth_l1(p0 - o0) + smooth_l1(p1 - o1) + smooth_l1(p2 - o2)
                   + smooth_l1(p3 - o3) + smooth_l1(p4 - o4) + smooth_l1(p5 - o5)
                   + smooth_l1(p6 - o6);
        }
        local = GAIN_F * reg_m * (1.0f / 14.0f);
    }

    // ---- reduction: warp shuffle, then one smem pass ----
    #pragma unroll
    for (int s = 16; s > 0; s >>= 1)
        local += __shfl_xor_sync(0xFFFFFFFFu, local, s);

    __shared__ float wsum[NWARP];
    const int wid = tid >> 5;
    const int lid = tid & 31;
    if (lid == 0) wsum[wid] = local;
    __syncthreads();

    if (wid == 0) {
        float v = (lid < NWARP) ? wsum[lid] : 0.0f;
        #pragma unroll
        for (int s = 8; s > 0; s >>= 1)
            v += __shfl_xor_sync(0xFFFFFFFFu, v, s);
        if (lid == 0) out[0] = v;
    }
}

extern "C" void kernel_launch(void* const* d_in, const int* in_sizes, int n_in,
                              void* d_out, int out_size) {
    const float* ref_boxes    = (const float*)d_in[0];
    const float* pred_class   = (const float*)d_in[1];
    const float* pred_regress = (const float*)d_in[2];
    const float* anchor       = (const float*)d_in[3];
    const int*   pos_idx      = (const int*)d_in[4];
    const int*   neg_idx      = (const int*)d_in[5];
    const int*   reg_idx      = (const int*)d_in[6];
    float* out = (float*)d_out;

    loss_total_kernel<<<1, NTHR>>>(ref_boxes, pred_class, pred_regress, anchor,
                                   pos_idx, neg_idx, reg_idx, out);
}